// round 2
// baseline (speedup 1.0000x reference)
#include <cuda_runtime.h>
#include <cstdint>

#define NN   50000
#define BB   2
#define FIN  128
#define FOUT 64
#define OC   128          // B*FOUT = gather row width = concatenated weight cols
#define EE   800000
#define ROWS (BB * NN)    // 100000

// Scratch (allocation-free rule: __device__ globals)
__device__ float g_xt[NN * OC];   // x@W laid out as (n, b*FOUT + o)  -- gather source
__device__ float g_agg[NN * OC];  // scatter destination

// ---------------------------------------------------------------------------
// Fused GEMM: per row r=(b,n): xt[n][b*64+o] = x[b][n][:]·W[:,o]
//                              out[b][n][o]  = x[b][n][:]·Wself[:,o] + bias[o]
// Warp processes 8 rows; lane owns output-column pairs (2l,2l+1) and
// (64+2l, 64+2l+1). Packed fp32 math via fma.rn.f32x2: each 64-bit acc holds
// two independent column sums (no horizontal reduce needed).
// ---------------------------------------------------------------------------
__global__ __launch_bounds__(128) void gemm_kernel(
    const float* __restrict__ x, const float* __restrict__ W,
    const float* __restrict__ Wself, const float* __restrict__ bself,
    float* __restrict__ out)
{
    extern __shared__ float ws[];   // ws[f*128 + c]: c<64 -> W[f][c], c>=64 -> Wself[f][c-64]
    int t = threadIdx.x;
    for (int idx = t; idx < FIN * 128; idx += 128) {
        int f = idx >> 7, c = idx & 127;
        ws[idx] = (c < 64) ? W[(f << 6) + c] : Wself[(f << 6) + (c - 64)];
    }
    __syncthreads();

    int lane = t & 31;
    long warp = (long)blockIdx.x * 4 + (t >> 5);
    long r0 = warp << 3;                       // 8 consecutive rows, same b (50000 % 8 == 0)
    const float* xp = x + r0 * FIN;

    unsigned long long acc0[8], acc1[8];
    #pragma unroll
    for (int i = 0; i < 8; i++) { acc0[i] = 0ull; acc1[i] = 0ull; }

    const int c0 = lane * 2;                   // my column pair base
    const float* wsp = ws + c0;

    for (int fc = 0; fc < FIN; fc += 4) {
        float4 xv[8];
        #pragma unroll
        for (int i = 0; i < 8; i++)
            xv[i] = *(const float4*)(xp + i * FIN + fc);   // broadcast LDG.128, L1-hit

        #pragma unroll
        for (int j = 0; j < 4; j++) {
            unsigned long long w0 = *(const unsigned long long*)(wsp + (fc + j) * 128);
            unsigned long long w1 = *(const unsigned long long*)(wsp + (fc + j) * 128 + 64);
            #pragma unroll
            for (int i = 0; i < 8; i++) {
                float xf = (j == 0) ? xv[i].x : (j == 1) ? xv[i].y : (j == 2) ? xv[i].z : xv[i].w;
                unsigned long long xx;
                asm("mov.b64 %0, {%1, %1};" : "=l"(xx) : "f"(xf));
                asm("fma.rn.f32x2 %0, %1, %2, %0;" : "+l"(acc0[i]) : "l"(xx), "l"(w0));
                asm("fma.rn.f32x2 %0, %1, %2, %0;" : "+l"(acc1[i]) : "l"(xx), "l"(w1));
            }
        }
    }

    int b  = (int)(r0 / NN);
    int n0 = (int)(r0 % NN);
    float2 bb = *(const float2*)(bself + c0);
    #pragma unroll
    for (int i = 0; i < 8; i++) {
        int n = n0 + i;
        float2 v0, v1;
        asm("mov.b64 {%0, %1}, %2;" : "=f"(v0.x), "=f"(v0.y) : "l"(acc0[i]));
        asm("mov.b64 {%0, %1}, %2;" : "=f"(v1.x), "=f"(v1.y) : "l"(acc1[i]));
        *(float2*)(g_xt + (long)n * OC + b * FOUT + c0) = v0;          // gather source
        v1.x += bb.x; v1.y += bb.y;                                     // self path + bias
        *(float2*)(out + ((long)b * NN + n) * FOUT + c0) = v1;
    }
}

// ---------------------------------------------------------------------------
// Edge scatter: one warp per edge. Lane l handles floats [4l,4l+4) of the
// 128-float row. Vector RED (red.global.add.v4.f32) quarters atomic op count.
// ---------------------------------------------------------------------------
__global__ __launch_bounds__(256) void scatter_kernel(
    const int* __restrict__ erow, const int* __restrict__ ecol,
    const float* __restrict__ eval)
{
    int e = blockIdx.x * 8 + (threadIdx.x >> 5);   // 800000 / 8 = 100000 blocks, exact
    int lane = threadIdx.x & 31;
    int r = erow[e], c = ecol[e];
    float v = eval[e];
    float4 s = *(const float4*)(g_xt + (long)c * OC + lane * 4);
    float* dst = g_agg + (long)r * OC + lane * 4;
    asm volatile("red.global.add.v4.f32 [%0], {%1, %2, %3, %4};"
                 :: "l"(dst), "f"(s.x * v), "f"(s.y * v), "f"(s.z * v), "f"(s.w * v)
                 : "memory");
}

// ---------------------------------------------------------------------------
// Epilogue: out[b][n][o] = relu(out[b][n][o] + agg[n][b*64+o])
// ---------------------------------------------------------------------------
__global__ __launch_bounds__(256) void epilogue_kernel(float* __restrict__ out)
{
    long i = (long)blockIdx.x * 256 + threadIdx.x;   // 1.6M float4 units, exact grid
    int  o4   = (int)(i & 15) * 4;
    long rest = i >> 4;                              // b*NN + n
    int  n = (int)(rest % NN);
    int  b = (int)(rest / NN);
    float4 a = *(const float4*)(g_agg + (long)n * OC + b * FOUT + o4);
    float4 s = *(float4*)(out + i * 4);
    s.x = fmaxf(s.x + a.x, 0.f);
    s.y = fmaxf(s.y + a.y, 0.f);
    s.z = fmaxf(s.z + a.z, 0.f);
    s.w = fmaxf(s.w + a.w, 0.f);
    *(float4*)(out + i * 4) = s;
}

extern "C" void kernel_launch(void* const* d_in, const int* in_sizes, int n_in,
                              void* d_out, int out_size)
{
    const float* x     = (const float*)d_in[0];
    const float* W     = (const float*)d_in[1];
    const float* Wself = (const float*)d_in[2];
    const float* bself = (const float*)d_in[3];
    const int*   erow  = (const int*)d_in[4];
    const int*   ecol  = (const int*)d_in[5];
    const float* eval  = (const float*)d_in[6];
    float* out = (float*)d_out;

    void* aggp = nullptr;
    cudaGetSymbolAddress(&aggp, g_agg);
    cudaMemsetAsync(aggp, 0, (size_t)NN * OC * sizeof(float), 0);

    cudaFuncSetAttribute(gemm_kernel, cudaFuncAttributeMaxDynamicSharedMemorySize, 65536);
    gemm_kernel<<<ROWS / 32, 128, 65536>>>(x, W, Wself, bself, out);   // 3125 blocks

    scatter_kernel<<<EE / 8, 256>>>(erow, ecol, eval);                 // 100000 blocks

    epilogue_kernel<<<(long)BB * NN * FOUT / 4 / 256, 256>>>(out);     // 6250 blocks
}

// round 3
// speedup vs baseline: 1.0017x; 1.0017x over previous
#include <cuda_runtime.h>
#include <cstdint>

#define NN   50000
#define BB   2
#define FIN  128
#define FOUT 64
#define OC   128          // B*FOUT = gather row width = concatenated weight cols
#define EE   800000
#define ROWS (BB * NN)    // 100000

// Scratch (allocation-free rule: __device__ globals)
__device__ float g_xt[NN * OC];   // x@W laid out as (n, b*FOUT + o)  -- gather source
__device__ float g_agg[NN * OC];  // scatter destination

// ---------------------------------------------------------------------------
// Fused GEMM: per row r=(b,n): xt[n][b*64+o] = x[b][n][:]·W[:,o]
//                              out[b][n][o]  = x[b][n][:]·Wself[:,o] + bias[o]
// Warp processes 8 rows; lane owns output-column pairs (2l,2l+1) and
// (64+2l, 64+2l+1). Packed fp32 math via fma.rn.f32x2: each 64-bit acc holds
// two independent column sums (no horizontal reduce needed).
// ---------------------------------------------------------------------------
__global__ __launch_bounds__(128) void gemm_kernel(
    const float* __restrict__ x, const float* __restrict__ W,
    const float* __restrict__ Wself, const float* __restrict__ bself,
    float* __restrict__ out)
{
    extern __shared__ float ws[];   // ws[f*128 + c]: c<64 -> W[f][c], c>=64 -> Wself[f][c-64]
    int t = threadIdx.x;
    for (int idx = t; idx < FIN * 128; idx += 128) {
        int f = idx >> 7, c = idx & 127;
        ws[idx] = (c < 64) ? W[(f << 6) + c] : Wself[(f << 6) + (c - 64)];
    }
    __syncthreads();

    int lane = t & 31;
    long warp = (long)blockIdx.x * 4 + (t >> 5);
    long r0 = warp << 3;                       // 8 consecutive rows, same b (50000 % 8 == 0)
    const float* xp = x + r0 * FIN;

    unsigned long long acc0[8], acc1[8];
    #pragma unroll
    for (int i = 0; i < 8; i++) { acc0[i] = 0ull; acc1[i] = 0ull; }

    const int c0 = lane * 2;                   // my column pair base
    const float* wsp = ws + c0;

    for (int fc = 0; fc < FIN; fc += 4) {
        float4 xv[8];
        #pragma unroll
        for (int i = 0; i < 8; i++)
            xv[i] = *(const float4*)(xp + i * FIN + fc);   // broadcast LDG.128, L1-hit

        #pragma unroll
        for (int j = 0; j < 4; j++) {
            unsigned long long w0 = *(const unsigned long long*)(wsp + (fc + j) * 128);
            unsigned long long w1 = *(const unsigned long long*)(wsp + (fc + j) * 128 + 64);
            #pragma unroll
            for (int i = 0; i < 8; i++) {
                float xf = (j == 0) ? xv[i].x : (j == 1) ? xv[i].y : (j == 2) ? xv[i].z : xv[i].w;
                unsigned long long xx;
                asm("mov.b64 %0, {%1, %1};" : "=l"(xx) : "f"(xf));
                asm("fma.rn.f32x2 %0, %1, %2, %0;" : "+l"(acc0[i]) : "l"(xx), "l"(w0));
                asm("fma.rn.f32x2 %0, %1, %2, %0;" : "+l"(acc1[i]) : "l"(xx), "l"(w1));
            }
        }
    }

    int b  = (int)(r0 / NN);
    int n0 = (int)(r0 % NN);
    float2 bb = *(const float2*)(bself + c0);
    #pragma unroll
    for (int i = 0; i < 8; i++) {
        int n = n0 + i;
        float2 v0, v1;
        asm("mov.b64 {%0, %1}, %2;" : "=f"(v0.x), "=f"(v0.y) : "l"(acc0[i]));
        asm("mov.b64 {%0, %1}, %2;" : "=f"(v1.x), "=f"(v1.y) : "l"(acc1[i]));
        *(float2*)(g_xt + (long)n * OC + b * FOUT + c0) = v0;          // gather source
        v1.x += bb.x; v1.y += bb.y;                                     // self path + bias
        *(float2*)(out + ((long)b * NN + n) * FOUT + c0) = v1;
    }
}

// ---------------------------------------------------------------------------
// Edge scatter: one warp per edge. Lane l handles floats [4l,4l+4) of the
// 128-float row. Vector RED (red.global.add.v4.f32) quarters atomic op count.
// ---------------------------------------------------------------------------
__global__ __launch_bounds__(256) void scatter_kernel(
    const int* __restrict__ erow, const int* __restrict__ ecol,
    const float* __restrict__ eval)
{
    int e = blockIdx.x * 8 + (threadIdx.x >> 5);   // 800000 / 8 = 100000 blocks, exact
    int lane = threadIdx.x & 31;
    int r = erow[e], c = ecol[e];
    float v = eval[e];
    float4 s = *(const float4*)(g_xt + (long)c * OC + lane * 4);
    float* dst = g_agg + (long)r * OC + lane * 4;
    asm volatile("red.global.add.v4.f32 [%0], {%1, %2, %3, %4};"
                 :: "l"(dst), "f"(s.x * v), "f"(s.y * v), "f"(s.z * v), "f"(s.w * v)
                 : "memory");
}

// ---------------------------------------------------------------------------
// Epilogue: out[b][n][o] = relu(out[b][n][o] + agg[n][b*64+o])
// ---------------------------------------------------------------------------
__global__ __launch_bounds__(256) void epilogue_kernel(float* __restrict__ out)
{
    long i = (long)blockIdx.x * 256 + threadIdx.x;   // 1.6M float4 units, exact grid
    int  o4   = (int)(i & 15) * 4;
    long rest = i >> 4;                              // b*NN + n
    int  n = (int)(rest % NN);
    int  b = (int)(rest / NN);
    float4 a = *(const float4*)(g_agg + (long)n * OC + b * FOUT + o4);
    float4 s = *(float4*)(out + i * 4);
    s.x = fmaxf(s.x + a.x, 0.f);
    s.y = fmaxf(s.y + a.y, 0.f);
    s.z = fmaxf(s.z + a.z, 0.f);
    s.w = fmaxf(s.w + a.w, 0.f);
    *(float4*)(out + i * 4) = s;
}

extern "C" void kernel_launch(void* const* d_in, const int* in_sizes, int n_in,
                              void* d_out, int out_size)
{
    const float* x     = (const float*)d_in[0];
    const float* W     = (const float*)d_in[1];
    const float* Wself = (const float*)d_in[2];
    const float* bself = (const float*)d_in[3];
    const int*   erow  = (const int*)d_in[4];
    const int*   ecol  = (const int*)d_in[5];
    const float* eval  = (const float*)d_in[6];
    float* out = (float*)d_out;

    void* aggp = nullptr;
    cudaGetSymbolAddress(&aggp, g_agg);
    cudaMemsetAsync(aggp, 0, (size_t)NN * OC * sizeof(float), 0);

    cudaFuncSetAttribute(gemm_kernel, cudaFuncAttributeMaxDynamicSharedMemorySize, 65536);
    gemm_kernel<<<ROWS / 32, 128, 65536>>>(x, W, Wself, bself, out);   // 3125 blocks

    scatter_kernel<<<EE / 8, 256>>>(erow, ecol, eval);                 // 100000 blocks

    epilogue_kernel<<<(long)BB * NN * FOUT / 4 / 256, 256>>>(out);     // 6250 blocks
}